// round 6
// baseline (speedup 1.0000x reference)
#include <cuda_runtime.h>
#include <cuda_fp16.h>
#include <cstdint>
#include <cstddef>

#define BATCH   8
#define NODES   2048
#define IN_DIM  64
#define HEADS   4
#define OUTD    32
#define UDIM    1024
#define NNB     32

typedef unsigned long long ULL;

// scratch: pre-split fp16 (hi/lo) operands, packed per head: [h*64 + part*32 + d]
__device__ __half g_Qh[BATCH * NODES * 256];   // Q pre-scaled by 1/sqrt(32)
__device__ __half g_Kh[BATCH * UDIM  * 256];
__device__ float  g_S [BATCH * NODES * UDIM];  // scores (L2-hot roundtrip)

#define FMA2(a, x, y) asm("fma.rn.f32x2 %0, %1, %2, %0;" : "+l"(a) : "l"(x), "l"(y))
#define UNPACK2(lo, hi, v) asm("mov.b64 {%0,%1}, %2;" : "=f"(lo), "=f"(hi) : "l"(v))
#define CP16(dst, src) asm volatile("cp.async.cg.shared.global [%0], [%1], 16;" :: "r"(dst), "l"(src))
#define CPCOMMIT()     asm volatile("cp.async.commit_group;" ::: "memory")
#define CPWAIT0()      asm volatile("cp.async.wait_group 0;" ::: "memory")

__device__ __forceinline__ uint32_t smem_u32(const void* p) {
    uint32_t a;
    asm("{ .reg .u64 t; cvta.to.shared.u64 t, %1; cvt.u32.u64 %0, t; }" : "=r"(a) : "l"(p));
    return a;
}

// ---------------------------------------------------------------------------
// Kernel 1: QK projection + fp16 hi/lo split, FFMA2 (f32x2) inner product.
//   Blocks [0,2048):    Q (8b x 256 tiles x 8 rows)
//   Blocks [2048,3072): K (8b x 128 tiles x 8 rows), first 1024 nodes
// ---------------------------------------------------------------------------
__global__ void __launch_bounds__(128) qk_kernel(
    const float* __restrict__ x,
    const float* __restrict__ Wq, const float* __restrict__ bq,
    const float* __restrict__ Wk, const float* __restrict__ bk)
{
    __shared__ float xs[8][64];

    const bool isK = (blockIdx.x >= 2048);
    int b, row0;
    const float* W; const float* bias;
    if (!isK) { b = blockIdx.x >> 8;             row0 = (blockIdx.x & 255) << 3; W = Wq; bias = bq; }
    else      { int id = blockIdx.x - 2048; b = id >> 7; row0 = (id & 127) << 3;  W = Wk; bias = bk; }

    const int c = threadIdx.x;
    const float* xb = x + ((size_t)b * NODES + row0) * IN_DIM;
    for (int k = threadIdx.x; k < 8 * 64; k += 128)
        xs[k >> 6][k & 63] = xb[k];

    // W row as 32 packed f32x2
    ULL w2[32];
    const ULL* Wr = (const ULL*)(W + (size_t)c * IN_DIM);
#pragma unroll
    for (int i = 0; i < 32; i++) w2[i] = Wr[i];
    const float bb = bias[c];
    __syncthreads();

    const float scale = isK ? 1.0f : 0.17677669529663687f;
    const int col = ((c >> 5) << 6) + (c & 31);              // h*64 + d
    __half* dst = (isK ? g_Kh : g_Qh) +
                  ((size_t)b * (isK ? UDIM : NODES) + row0) * 256;

#pragma unroll
    for (int r = 0; r < 8; r++) {
        const ULL* xr = (const ULL*)xs[r];
        ULL a0 = 0ull, a1 = 0ull, a2 = 0ull, a3 = 0ull;
#pragma unroll
        for (int i = 0; i < 8; i++) {
            FMA2(a0, xr[i],      w2[i]);
            FMA2(a1, xr[8 + i],  w2[8 + i]);
            FMA2(a2, xr[16 + i], w2[16 + i]);
            FMA2(a3, xr[24 + i], w2[24 + i]);
        }
        float l0, h0, l1, h1, l2, h2, l3, h3;
        UNPACK2(l0, h0, a0); UNPACK2(l1, h1, a1);
        UNPACK2(l2, h2, a2); UNPACK2(l3, h3, a3);
        float acc = (bb + ((l0 + h0) + (l1 + h1)) + ((l2 + h2) + (l3 + h3))) * scale;
        __half hh = __float2half_rn(acc);
        float  lo = acc - __half2float(hh);
        dst[(size_t)r * 256 + col]      = hh;
        dst[(size_t)r * 256 + col + 32] = __float2half_rn(lo);
    }
}

// ---------------------------------------------------------------------------
// Kernel 2: fused HMMA scores + head-mix + zero-fill + top-32 + scatter.
// Block = (b, 64 n-rows), 256 threads (8 warps = 4n x 2u), 2 blocks/SM.
// 32 u-chunks of 32, cp.async double-buffered K. 3 combos (hh, hl, lh).
// Output zero-fill of the block's OWN rows interleaved into the chunk loop;
// topk tail scatters into them (scores re-read from L2-hot g_S).
// ---------------------------------------------------------------------------
#define SKROW   528                    // 256 halfs + 16B pad
#define SMQ     0                      // 64*528 = 33792
#define SMK     33792                  // 2 * 32*528 = 33792
#define KBUF    16896
#define SMEMSZ  67584

__device__ __forceinline__ void mma_f16(float* c, const uint32_t* a, const uint32_t* b) {
    asm volatile("mma.sync.aligned.m16n8k16.row.col.f32.f16.f16.f32 "
        "{%0,%1,%2,%3}, {%4,%5,%6,%7}, {%8,%9}, {%0,%1,%2,%3};"
        : "+f"(c[0]), "+f"(c[1]), "+f"(c[2]), "+f"(c[3])
        : "r"(a[0]), "r"(a[1]), "r"(a[2]), "r"(a[3]), "r"(b[0]), "r"(b[1]));
}

__device__ __forceinline__ void fillK_async(uint32_t smk, int b, int ck, int buf, int tid) {
    const char* src = (const char*)(g_Kh + ((size_t)(b * UDIM + ck * 32)) * 256);
    const uint32_t dst = smk + buf * KBUF;
#pragma unroll
    for (int it = 0; it < 4; it++) {
        int idx = it * 256 + tid;            // 32 rows x 32 x 16B
        int row = idx >> 5, j = idx & 31;
        CP16(dst + row * SKROW + j * 16, src + row * 512 + j * 16);
    }
}

__global__ void __launch_bounds__(256, 2) score_topk_kernel(
    const float* __restrict__ mlp_w, const float* __restrict__ mlp_b,
    float* __restrict__ out)
{
    extern __shared__ __align__(16) char sm[];
    const uint32_t smb = smem_u32(sm);
    const int tid = threadIdx.x, lane = tid & 31, wid = tid >> 5;
    const int wr0 = (wid & 3) << 4;           // warp n-offset (0..48)
    const int uw0 = (wid >> 2) << 4;          // warp u-offset within chunk (0/16)
    const int b  = blockIdx.x >> 5;
    const int n0 = (blockIdx.x & 31) << 6;

    // async stage Q tile (64 rows x 512B) + K chunk 0
    {
        const char* qsrc = (const char*)(g_Qh + ((size_t)(b * NODES + n0)) * 256);
#pragma unroll
        for (int it = 0; it < 8; it++) {
            int idx = it * 256 + tid;
            int row = idx >> 5, j = idx & 31;
            CP16(smb + SMQ + row * SKROW + j * 16, qsrc + row * 512 + j * 16);
        }
    }
    fillK_async(smb + SMK, b, 0, 0, tid);
    CPCOMMIT();

    float mm[4][4], mb_[4];
#pragma unroll
    for (int o = 0; o < 4; o++) {
        mb_[o] = mlp_b[o];
#pragma unroll
        for (int h = 0; h < 4; h++) mm[o][h] = mlp_w[o * 4 + h];
    }

    CPWAIT0();
    __syncthreads();

    // A fragments (16 rows/warp), cached for all 32 chunks
    uint32_t aF[4][2][2][4];                  // [head][part][kstep][frag]
    {
        const char* qb = sm + SMQ + (wr0 + (lane >> 2)) * SKROW;
#pragma unroll
        for (int h = 0; h < 4; h++)
#pragma unroll
            for (int p = 0; p < 2; p++)
#pragma unroll
                for (int s = 0; s < 2; s++) {
                    int off = (h * 64 + p * 32 + s * 16 + (lane & 3) * 2) * 2;
                    aF[h][p][s][0] = *(const uint32_t*)(qb + off);
                    aF[h][p][s][1] = *(const uint32_t*)(qb + off + 8 * SKROW);
                    aF[h][p][s][2] = *(const uint32_t*)(qb + off + 16);
                    aF[h][p][s][3] = *(const uint32_t*)(qb + off + 8 * SKROW + 16);
                }
    }

    for (int ck = 0; ck < 32; ck++) {
        const int buf = ck & 1;
        CPWAIT0();                             // chunk ck landed
        __syncthreads();                       // all warps done with buf^1
        if (ck + 1 < 32) { fillK_async(smb + SMK, b, ck + 1, buf ^ 1, tid); CPCOMMIT(); }

        // zero-fill 2 of this block's own output rows (hidden under compute)
        {
            const int zr = 2 * ck + (tid >> 7);
            float4* zp = (float4*)(out + ((size_t)(b * NODES + n0 + zr)) * NODES)
                         + (tid & 127) * 4;
            const float4 z4 = make_float4(0.f, 0.f, 0.f, 0.f);
            zp[0] = z4; zp[1] = z4; zp[2] = z4; zp[3] = z4;
        }

#pragma unroll
        for (int ut = 0; ut < 2; ut++) {
            float acc[4][4];
#pragma unroll
            for (int h = 0; h < 4; h++)
#pragma unroll
                for (int j = 0; j < 4; j++) acc[h][j] = 0.f;

            const char* kb = sm + SMK + buf * KBUF +
                             (uw0 + ut * 8 + (lane >> 2)) * SKROW;
#pragma unroll
            for (int h = 0; h < 4; h++) {
                uint32_t bh[2][2], bl[2][2];
#pragma unroll
                for (int s = 0; s < 2; s++) {
                    int offh = (h * 64 + s * 16 + (lane & 3) * 2) * 2;
                    bh[s][0] = *(const uint32_t*)(kb + offh);
                    bh[s][1] = *(const uint32_t*)(kb + offh + 16);
                    bl[s][0] = *(const uint32_t*)(kb + offh + 64);
                    bl[s][1] = *(const uint32_t*)(kb + offh + 64 + 16);
                }
#pragma unroll
                for (int s = 0; s < 2; s++) {
                    mma_f16(acc[h], aF[h][0][s], bh[s]);   // hh
                    mma_f16(acc[h], aF[h][0][s], bl[s]);   // hl
                    mma_f16(acc[h], aF[h][1][s], bh[s]);   // lh
                }
            }

            // epilogue -> g_S (coalesced float2; L2-hot for the tail)
            float s_[4];
#pragma unroll
            for (int j = 0; j < 4; j++) {
                float a0 = acc[0][j], a1 = acc[1][j];
                float a2 = acc[2][j], a3 = acc[3][j];
                float s = a0 + a1 + a2 + a3;
#pragma unroll
                for (int o = 0; o < 4; o++) {
                    float z = fmaf(mm[o][0], a0, fmaf(mm[o][1], a1,
                              fmaf(mm[o][2], a2, fmaf(mm[o][3], a3, mb_[o]))));
                    s += fmaxf(z, 0.f);
                }
                s_[j] = s;
            }
            float* sg = g_S + ((size_t)(b * NODES + n0 + wr0 + (lane >> 2))) * UDIM
                        + ck * 32 + uw0 + ut * 8 + (lane & 3) * 2;
            *(float2*)sg              = make_float2(s_[0], s_[1]);
            *(float2*)(sg + 8 * UDIM) = make_float2(s_[2], s_[3]);
        }
    }
    __syncthreads();   // g_S writes visible block-wide

    // ---- topk tail: 8 rows per warp, radix select; scatter into zeroed rows ----
    unsigned* base  = (unsigned*)(sm + SMK);
    unsigned* hist  = base + wid * 256;
    unsigned* ties  = base + 2048 + wid * 64;
    unsigned* found = base + 2560 + wid * 2;
    unsigned* tcnt  = base + 2576 + wid;

    for (int rr = 0; rr < 8; rr++) {
        const int row = wid * 8 + rr;
        const float* srow = g_S + ((size_t)(b * NODES + n0 + row)) * UDIM;
        float    vals[32];
        unsigned keys[32];
#pragma unroll
        for (int j = 0; j < 32; j++) {
            float v = srow[j * 32 + lane];
            vals[j] = v;
            unsigned u = __float_as_uint(v);
            keys[j] = u ^ (((unsigned)((int)u >> 31)) | 0x80000000u);
        }

        float* orow = out + ((size_t)(b * NODES + n0 + row)) * (size_t)NODES;

        unsigned prefix = 0;
        int needed = NNB;
        for (int shift = 24; shift >= 0; shift -= 8) {
            for (int t = lane; t < 256; t += 32) hist[t] = 0;
            __syncwarp();
            const unsigned hm = (shift == 24) ? 0u : (0xFFFFFFFFu << (shift + 8));
#pragma unroll
            for (int j = 0; j < 32; j++)
                if (((keys[j] ^ prefix) & hm) == 0)
                    atomicAdd(&hist[(keys[j] >> shift) & 255], 1u);
            __syncwarp();
            unsigned s = 0;
#pragma unroll
            for (int t = 0; t < 8; t++) s += hist[lane * 8 + t];
            unsigned rs = s;
#pragma unroll
            for (int off = 1; off < 32; off <<= 1) {
                unsigned v = __shfl_down_sync(0xffffffffu, rs, off);
                if (lane + off < 32) rs += v;
            }
            unsigned acc2 = rs - s;       // keys in strictly-higher buckets
            for (int t = 7; t >= 0; t--) {
                unsigned c = hist[lane * 8 + t];
                if ((int)acc2 < needed && needed <= (int)(acc2 + c)) {
                    found[0] = (unsigned)(lane * 8 + t);
                    found[1] = acc2;
                }
                acc2 += c;
            }
            __syncwarp();
            prefix |= found[0] << shift;
            needed -= (int)found[1];
            __syncwarp();
        }

        if (lane == 0) *tcnt = 0;
        __syncwarp();
#pragma unroll
        for (int j = 0; j < 32; j++) {
            if (keys[j] > prefix) orow[j * 32 + lane] = vals[j];
            else if (keys[j] == prefix) {
                unsigned p = atomicAdd(tcnt, 1u);
                if (p < 64) ties[p] = (unsigned)(j * 32 + lane);
            }
        }
        __syncwarp();
        if (lane == 0) {
            int cnt = *tcnt < 64 ? (int)*tcnt : 64;
            unsigned ku = (prefix & 0x80000000u) ? (prefix ^ 0x80000000u) : ~prefix;
            float kval = __uint_as_float(ku);
            for (int e = 0; e < needed; e++) {
                int bi = -1; unsigned bidx = 0xFFFFFFFFu;
                for (int t = 0; t < cnt; t++)
                    if (ties[t] < bidx) { bidx = ties[t]; bi = t; }
                if (bi >= 0) { orow[bidx] = kval; ties[bi] = 0xFFFFFFFFu; }
            }
        }
        __syncwarp();
    }
}

// ---------------------------------------------------------------------------
extern "C" void kernel_launch(void* const* d_in, const int* in_sizes, int n_in,
                              void* d_out, int out_size)
{
    const float* x     = (const float*)d_in[0];
    const float* Wq    = (const float*)d_in[1];
    const float* bq    = (const float*)d_in[2];
    const float* Wk    = (const float*)d_in[3];
    const float* bk    = (const float*)d_in[4];
    const float* mlp_w = (const float*)d_in[5];
    const float* mlp_b = (const float*)d_in[6];

    float* out = (float*)d_out;

    qk_kernel<<<3072, 128>>>(x, Wq, bq, Wk, bk);

    cudaFuncSetAttribute(score_topk_kernel,
                         cudaFuncAttributeMaxDynamicSharedMemorySize, SMEMSZ);
    score_topk_kernel<<<BATCH * (NODES / 64), 256, SMEMSZ>>>(mlp_w, mlp_b, out);
}

// round 7
// speedup vs baseline: 1.1670x; 1.1670x over previous
#include <cuda_runtime.h>
#include <cuda_fp16.h>
#include <cstdint>
#include <cstddef>

#define BATCH   8
#define NODES   2048
#define IN_DIM  64
#define HEADS   4
#define OUTD    32
#define UDIM    1024
#define NNB     32

// scratch: pre-split fp16 (hi/lo) operands, packed per head: [h*64 + part*32 + d]
__device__ __half g_Qh[BATCH * NODES * 256];   // Q pre-scaled by 1/sqrt(32)
__device__ __half g_Kh[BATCH * UDIM  * 256];
__device__ float  g_S [BATCH * NODES * UDIM];  // scores (L2-hot roundtrip)

#define CP16(dst, src) asm volatile("cp.async.cg.shared.global [%0], [%1], 16;" :: "r"(dst), "l"(src))
#define CPCOMMIT()     asm volatile("cp.async.commit_group;" ::: "memory")
#define CPWAIT0()      asm volatile("cp.async.wait_group 0;" ::: "memory")

__device__ __forceinline__ uint32_t smem_u32(const void* p) {
    uint32_t a;
    asm("{ .reg .u64 t; cvta.to.shared.u64 t, %1; cvt.u32.u64 %0, t; }" : "=r"(a) : "l"(p));
    return a;
}

// ---------------------------------------------------------------------------
// Kernel 1: QK projection + fp16 hi/lo split (R4-proven float4 version).
//   Blocks [0,1024):    Q (8b x 128 tiles x 16 rows)
//   Blocks [1024,1536): K (8b x 64 tiles x 16 rows), first 1024 nodes
// ---------------------------------------------------------------------------
__global__ void __launch_bounds__(128) qk_kernel(
    const float* __restrict__ x,
    const float* __restrict__ Wq, const float* __restrict__ bq,
    const float* __restrict__ Wk, const float* __restrict__ bk)
{
    __shared__ float xs[16][64];

    const bool isK = (blockIdx.x >= 1024);
    int b, row0;
    const float* W; const float* bias;
    if (!isK) { b = blockIdx.x >> 7;             row0 = (blockIdx.x & 127) << 4; W = Wq; bias = bq; }
    else      { int id = blockIdx.x - 1024; b = id >> 6; row0 = (id & 63) << 4;  W = Wk; bias = bk; }

    const int c = threadIdx.x;
    const float* xb = x + ((size_t)b * NODES + row0) * IN_DIM;
    for (int k = threadIdx.x; k < 16 * 64; k += 128)
        xs[k >> 6][k & 63] = xb[k];

    float4 w[16];
    const float4* Wr = (const float4*)(W + (size_t)c * IN_DIM);
#pragma unroll
    for (int i = 0; i < 16; i++) w[i] = Wr[i];
    const float bb = bias[c];
    __syncthreads();

    const float scale = isK ? 1.0f : 0.17677669529663687f;
    const int col = ((c >> 5) << 6) + (c & 31);              // h*64 + d
    __half* dst = (isK ? g_Kh : g_Qh) +
                  ((size_t)b * (isK ? UDIM : NODES) + row0) * 256;

#pragma unroll
    for (int r = 0; r < 16; r++) {
        const float4* xr = (const float4*)xs[r];
        float a0 = 0.f, a1 = 0.f, a2 = 0.f, a3 = 0.f;
#pragma unroll
        for (int i = 0; i < 4; i++) {
            float4 v0 = xr[i],     v1 = xr[4 + i];
            float4 v2 = xr[8 + i], v3 = xr[12 + i];
            a0 += v0.x * w[i].x      + v0.y * w[i].y      + v0.z * w[i].z      + v0.w * w[i].w;
            a1 += v1.x * w[4 + i].x  + v1.y * w[4 + i].y  + v1.z * w[4 + i].z  + v1.w * w[4 + i].w;
            a2 += v2.x * w[8 + i].x  + v2.y * w[8 + i].y  + v2.z * w[8 + i].z  + v2.w * w[8 + i].w;
            a3 += v3.x * w[12 + i].x + v3.y * w[12 + i].y + v3.z * w[12 + i].z + v3.w * w[12 + i].w;
        }
        float acc = (bb + (a0 + a1) + (a2 + a3)) * scale;
        __half hh = __float2half_rn(acc);
        float  lo = acc - __half2float(hh);
        dst[(size_t)r * 256 + col]      = hh;
        dst[(size_t)r * 256 + col + 32] = __float2half_rn(lo);
    }
}

// ---------------------------------------------------------------------------
// Kernel 2: fused HMMA scores + head-mix + zero-fill + top-32 + scatter.
// Block = (b, 32 n-rows), 256 threads (8 warps = 2n x 4u), 2 blocks/SM.
// 16 u-chunks of 64, cp.async double-buffered K. B frags via ldmatrix.x4.
// ---------------------------------------------------------------------------
#define SKROW   528                    // 512B row + 16B pad (bank offset 4/row)
#define SMQ     0                      // 32*528 = 16896
#define SMK     16896                  // 2 * 64*528 = 67584
#define KBUF    (64 * SKROW)
#define SMEMSZ  84480

__device__ __forceinline__ void mma_f16(float* c, const uint32_t* a, const uint32_t* b) {
    asm volatile("mma.sync.aligned.m16n8k16.row.col.f32.f16.f16.f32 "
        "{%0,%1,%2,%3}, {%4,%5,%6,%7}, {%8,%9}, {%0,%1,%2,%3};"
        : "+f"(c[0]), "+f"(c[1]), "+f"(c[2]), "+f"(c[3])
        : "r"(a[0]), "r"(a[1]), "r"(a[2]), "r"(a[3]), "r"(b[0]), "r"(b[1]));
}
__device__ __forceinline__ void ldsm_x4(uint32_t* r, uint32_t addr) {
    asm volatile("ldmatrix.sync.aligned.m8n8.x4.shared.b16 {%0,%1,%2,%3}, [%4];"
        : "=r"(r[0]), "=r"(r[1]), "=r"(r[2]), "=r"(r[3]) : "r"(addr));
}

__device__ __forceinline__ void fillK_async(uint32_t smk, int b, int ck, int buf, int tid) {
    const char* src = (const char*)(g_Kh + ((size_t)(b * UDIM + ck * 64)) * 256);
    const uint32_t dst = smk + buf * KBUF;
#pragma unroll
    for (int it = 0; it < 8; it++) {
        int idx = it * 256 + tid;            // 64 rows x 32 x 16B
        int row = idx >> 5, j = idx & 31;
        CP16(dst + row * SKROW + j * 16, src + row * 512 + j * 16);
    }
}

__global__ void __launch_bounds__(256, 2) score_topk_kernel(
    const float* __restrict__ mlp_w, const float* __restrict__ mlp_b,
    float* __restrict__ out)
{
    extern __shared__ __align__(16) char sm[];
    const uint32_t smb = smem_u32(sm);
    const int tid = threadIdx.x, lane = tid & 31, wid = tid >> 5;
    const int wr0 = (wid & 1) << 4;           // warp n-offset (0/16)
    const int uw0 = (wid >> 1) << 4;          // warp u-offset in chunk (0..48)
    const int b  = blockIdx.x >> 6;
    const int n0 = (blockIdx.x & 63) << 5;

    // async stage Q tile (32 rows x 512B) + K chunk 0
    {
        const char* qsrc = (const char*)(g_Qh + ((size_t)(b * NODES + n0)) * 256);
#pragma unroll
        for (int it = 0; it < 4; it++) {
            int idx = it * 256 + tid;
            int row = idx >> 5, j = idx & 31;
            CP16(smb + SMQ + row * SKROW + j * 16, qsrc + row * 512 + j * 16);
        }
    }
    fillK_async(smb + SMK, b, 0, 0, tid);
    CPCOMMIT();

    float mm[4][4], mb_[4];
#pragma unroll
    for (int o = 0; o < 4; o++) {
        mb_[o] = mlp_b[o];
#pragma unroll
        for (int h = 0; h < 4; h++) mm[o][h] = mlp_w[o * 4 + h];
    }

    CPWAIT0();
    __syncthreads();

    // A fragments (16 rows/warp), cached for all 16 chunks
    uint32_t aF[4][2][2][4];                  // [head][part][kstep][frag]
    {
        const char* qb = sm + SMQ + (wr0 + (lane >> 2)) * SKROW;
#pragma unroll
        for (int h = 0; h < 4; h++)
#pragma unroll
            for (int p = 0; p < 2; p++)
#pragma unroll
                for (int s = 0; s < 2; s++) {
                    int off = (h * 64 + p * 32 + s * 16 + (lane & 3) * 2) * 2;
                    aF[h][p][s][0] = *(const uint32_t*)(qb + off);
                    aF[h][p][s][1] = *(const uint32_t*)(qb + off + 8 * SKROW);
                    aF[h][p][s][2] = *(const uint32_t*)(qb + off + 16);
                    aF[h][p][s][3] = *(const uint32_t*)(qb + off + 8 * SKROW + 16);
                }
    }

    for (int ck = 0; ck < 16; ck++) {
        const int buf = ck & 1;
        CPWAIT0();                             // chunk ck landed
        __syncthreads();                       // all warps done with buf^1
        if (ck + 1 < 16) { fillK_async(smb + SMK, b, ck + 1, buf ^ 1, tid); CPCOMMIT(); }

        // zero-fill 2 of this block's own output rows (hidden under compute)
        {
            const int zr = 2 * ck + (tid >> 7);
            float4* zp = (float4*)(out + ((size_t)(b * NODES + n0 + zr)) * NODES)
                         + (tid & 127) * 4;
            const float4 z4 = make_float4(0.f, 0.f, 0.f, 0.f);
            zp[0] = z4; zp[1] = z4; zp[2] = z4; zp[3] = z4;
        }

#pragma unroll
        for (int ut = 0; ut < 2; ut++) {
            float acc[4][4];
#pragma unroll
            for (int h = 0; h < 4; h++)
#pragma unroll
                for (int j = 0; j < 4; j++) acc[h][j] = 0.f;

            // ldmatrix base: row = uw0+ut*8+(lane&7), tile col = (lane>>3)*16
            const uint32_t kbase = smb + SMK + buf * KBUF +
                                   (uw0 + ut * 8 + (lane & 7)) * SKROW +
                                   ((lane >> 3) << 4);
#pragma unroll
            for (int h = 0; h < 4; h++) {
                uint32_t bh[4], bl[4];
                ldsm_x4(bh, kbase + h * 128);        // hi: k0..31
                ldsm_x4(bl, kbase + h * 128 + 64);   // lo: k0..31
#pragma unroll
                for (int s = 0; s < 2; s++) {
                    mma_f16(acc[h], aF[h][0][s], bh + 2 * s);   // hh
                    mma_f16(acc[h], aF[h][0][s], bl + 2 * s);   // hl
                    mma_f16(acc[h], aF[h][1][s], bh + 2 * s);   // lh
                }
            }

            // epilogue -> g_S (coalesced float2; L2-hot for the tail)
            float s_[4];
#pragma unroll
            for (int j = 0; j < 4; j++) {
                float a0 = acc[0][j], a1 = acc[1][j];
                float a2 = acc[2][j], a3 = acc[3][j];
                float s = a0 + a1 + a2 + a3;
#pragma unroll
                for (int o = 0; o < 4; o++) {
                    float z = fmaf(mm[o][0], a0, fmaf(mm[o][1], a1,
                              fmaf(mm[o][2], a2, fmaf(mm[o][3], a3, mb_[o]))));
                    s += fmaxf(z, 0.f);
                }
                s_[j] = s;
            }
            float* sg = g_S + ((size_t)(b * NODES + n0 + wr0 + (lane >> 2))) * UDIM
                        + ck * 64 + uw0 + ut * 8 + (lane & 3) * 2;
            *(float2*)sg              = make_float2(s_[0], s_[1]);
            *(float2*)(sg + 8 * UDIM) = make_float2(s_[2], s_[3]);
        }
    }
    __syncthreads();   // g_S writes + zero-fill visible block-wide

    // ---- topk tail: 4 rows per warp, radix select; scatter into zeroed rows ----
    unsigned* base  = (unsigned*)(sm + SMK);
    unsigned* hist  = base + wid * 256;
    unsigned* ties  = base + 2048 + wid * 64;
    unsigned* found = base + 2560 + wid * 2;
    unsigned* tcnt  = base + 2576 + wid;

    for (int rr = 0; rr < 4; rr++) {
        const int row = wid * 4 + rr;
        const float* srow = g_S + ((size_t)(b * NODES + n0 + row)) * UDIM;
        float    vals[32];
        unsigned keys[32];
#pragma unroll
        for (int j = 0; j < 32; j++) {
            float v = srow[j * 32 + lane];
            vals[j] = v;
            unsigned u = __float_as_uint(v);
            keys[j] = u ^ (((unsigned)((int)u >> 31)) | 0x80000000u);
        }

        float* orow = out + ((size_t)(b * NODES + n0 + row)) * (size_t)NODES;

        unsigned prefix = 0;
        int needed = NNB;
        for (int shift = 24; shift >= 0; shift -= 8) {
            for (int t = lane; t < 256; t += 32) hist[t] = 0;
            __syncwarp();
            const unsigned hm = (shift == 24) ? 0u : (0xFFFFFFFFu << (shift + 8));
#pragma unroll
            for (int j = 0; j < 32; j++)
                if (((keys[j] ^ prefix) & hm) == 0)
                    atomicAdd(&hist[(keys[j] >> shift) & 255], 1u);
            __syncwarp();
            unsigned s = 0;
#pragma unroll
            for (int t = 0; t < 8; t++) s += hist[lane * 8 + t];
            unsigned rs = s;
#pragma unroll
            for (int off = 1; off < 32; off <<= 1) {
                unsigned v = __shfl_down_sync(0xffffffffu, rs, off);
                if (lane + off < 32) rs += v;
            }
            unsigned acc2 = rs - s;       // keys in strictly-higher buckets
            for (int t = 7; t >= 0; t--) {
                unsigned c = hist[lane * 8 + t];
                if ((int)acc2 < needed && needed <= (int)(acc2 + c)) {
                    found[0] = (unsigned)(lane * 8 + t);
                    found[1] = acc2;
                }
                acc2 += c;
            }
            __syncwarp();
            prefix |= found[0] << shift;
            needed -= (int)found[1];
            __syncwarp();
        }

        if (lane == 0) *tcnt = 0;
        __syncwarp();
#pragma unroll
        for (int j = 0; j < 32; j++) {
            if (keys[j] > prefix) orow[j * 32 + lane] = vals[j];
            else if (keys[j] == prefix) {
                unsigned p = atomicAdd(tcnt, 1u);
                if (p < 64) ties[p] = (unsigned)(j * 32 + lane);
            }
        }
        __syncwarp();
        if (lane == 0) {
            int cnt = *tcnt < 64 ? (int)*tcnt : 64;
            unsigned ku = (prefix & 0x80000000u) ? (prefix ^ 0x80000000u) : ~prefix;
            float kval = __uint_as_float(ku);
            for (int e = 0; e < needed; e++) {
                int bi = -1; unsigned bidx = 0xFFFFFFFFu;
                for (int t = 0; t < cnt; t++)
                    if (ties[t] < bidx) { bidx = ties[t]; bi = t; }
                if (bi >= 0) { orow[bidx] = kval; ties[bi] = 0xFFFFFFFFu; }
            }
        }
        __syncwarp();
    }
}

// ---------------------------------------------------------------------------
extern "C" void kernel_launch(void* const* d_in, const int* in_sizes, int n_in,
                              void* d_out, int out_size)
{
    const float* x     = (const float*)d_in[0];
    const float* Wq    = (const float*)d_in[1];
    const float* bq    = (const float*)d_in[2];
    const float* Wk    = (const float*)d_in[3];
    const float* bk    = (const float*)d_in[4];
    const float* mlp_w = (const float*)d_in[5];
    const float* mlp_b = (const float*)d_in[6];

    float* out = (float*)d_out;

    qk_kernel<<<1536, 128>>>(x, Wq, bq, Wk, bk);

    cudaFuncSetAttribute(score_topk_kernel,
                         cudaFuncAttributeMaxDynamicSharedMemorySize, SMEMSZ);
    score_topk_kernel<<<BATCH * (NODES / 32), 256, SMEMSZ>>>(mlp_w, mlp_b, out);
}